// round 11
// baseline (speedup 1.0000x reference)
#include <cuda_runtime.h>

#define BATCH 128
#define NIN   1024
#define NOUT  512
#define JT    64
#define NJT   (NOUT / JT)    // 8
#define NCH   37             // 36 chunks of 28 + 1 of 16 ; grid 8*37 = 296 = 148*2
#define NBLK  296
#define NTHR  (NBLK * 256)   // 75776
#define SRMAX 14
#define E0    2.1245f
#define LN2   0.69314718f
#define W_F4  131072         // float4 count per w array
#define X_F4  32768          // float4 count of x
#define ROWF4 (NOUT / 4)     // 128 float4 per batch-row

__device__ int          g_max_bits;              // zero-init; monotone -> replay-stable
__device__ unsigned int g_gate1;                 // monotone ticket counter (never reset)
__device__ unsigned int g_colcnt[NJT];           // per-column monotone counters
__device__ float        g_lvT[NIN * BATCH];      // transposed clamped lg2 input
__device__ float        g_partial[NCH * BATCH * NOUT];

__device__ __forceinline__ float ex2f_(float x) {
    float y; asm("ex2.approx.f32 %0, %1;" : "=f"(y) : "f"(x)); return y;
}
__device__ __forceinline__ float lg2f_(float x) {
    float y; asm("lg2.approx.f32 %0, %1;" : "=f"(y) : "f"(x)); return y;
}

// Monotone-ticket global barrier (replay-safe, no reset needed).
__device__ __forceinline__ void global_gate(unsigned int* ctr, int tid) {
    __syncthreads();
    if (tid == 0) {
        __threadfence();
        unsigned int t = atomicAdd(ctr, 1u);
        unsigned int target = (t / NBLK + 1u) * NBLK;
        while (*reinterpret_cast<volatile unsigned int*>(ctr) < target)
            __nanosleep(32);
    }
    __syncthreads();
    __threadfence();
}

// ---------------------------------------------------------------------------
// Staged compute: Taylor K=4, register-blocked 4j x 8b per thread (FFMA-bound)
// ---------------------------------------------------------------------------
template<int SR>
__device__ __forceinline__ void stage_rows(
    const float* __restrict__ w_pos, const float* __restrict__ w_neg,
    const float* __restrict__ n_param,
    float* phi_s, float* coef_s,
    int i0, int j0, int tid, int jq, int bbase, float cG, float (*acc)[8])
{
    __syncthreads();
    // ---- stage phi[ii][k][b]
    constexpr int TOT_LV = SR * BATCH;
    #pragma unroll
    for (int r = 0; r < (TOT_LV + 255) / 256; r++) {
        int idx = r * 256 + tid;
        if ((TOT_LV % 256 == 0) || idx < TOT_LV) {
            int ii = idx >> 7;
            int b  = idx & 127;
            float lv = g_lvT[(i0 + ii) * BATCH + b];
            float p0 = ex2f_(E0 * lv);
            float L  = lv * LN2;
            float p1 = p0 * L;
            float p2 = p1 * (L * 0.5f);
            float p3 = p2 * (L * 0.33333333f);
            float* dst = &phi_s[ii * 512 + b];
            dst[0]   = p0;
            dst[128] = p1;
            dst[256] = p2;
            dst[384] = p3;
        }
    }
    // ---- stage C_k at coef[ii][k][j]
    constexpr int TOT_CF = SR * JT;
    #pragma unroll
    for (int r = 0; r < (TOT_CF + 255) / 256; r++) {
        int idx = r * 256 + tid;
        if ((TOT_CF % 256 == 0) || idx < TOT_CF) {
            int ii = idx >> 6, jj = idx & 63;
            int i = i0 + ii, j = j0 + jj;
            float cp = 0.5f * (fabsf(w_pos[i * NOUT + j]) + cG);
            float cn = 0.5f * (fabsf(w_neg[i * NOUT + j]) + cG);
            float2 np = reinterpret_cast<const float2*>(n_param)[i * NOUT + j];
            float ep = lg2f_(np.x) + 1.0f - E0;
            float en = lg2f_(np.y) + 1.0f - E0;
            float* dst = &coef_s[ii * 256 + jj];
            dst[0]   = cp - cn;
            dst[64]  = cp * ep - cn * en;
            dst[128] = cp * ep * ep - cn * en * en;
            dst[192] = cp * ep * ep * ep - cn * en * en * en;
        }
    }
    __syncthreads();

    // ---- inner loop: 12 LDS.128 / 128 FFMA per thread*ii -> FFMA-bound
    #pragma unroll 2
    for (int ii = 0; ii < SR; ii++) {
        const float* cb = &coef_s[ii * 256 + jq * 4];
        const float* pb = &phi_s[ii * 512 + bbase];
        #pragma unroll
        for (int k = 0; k < 4; k++) {
            float4 c  = *reinterpret_cast<const float4*>(cb + k * 64);
            float4 pa = *reinterpret_cast<const float4*>(pb + k * 128);
            float4 pc = *reinterpret_cast<const float4*>(pb + k * 128 + 4);
            const float cv[4] = {c.x, c.y, c.z, c.w};
            const float pv[8] = {pa.x, pa.y, pa.z, pa.w, pc.x, pc.y, pc.z, pc.w};
            #pragma unroll
            for (int j = 0; j < 4; j++)
                #pragma unroll
                for (int b = 0; b < 8; b++)
                    acc[j][b] = fmaf(cv[j], pv[b], acc[j][b]);
        }
    }
}

// ---------------------------------------------------------------------------
// Single persistent kernel: prologue (max|w| + lvT) -> gate1 -> compute ->
// store partials -> per-column ticket; the 37th arrival of each j-column
// reduces that column (L2-hot, overlapped with other columns' compute).
// ---------------------------------------------------------------------------
__global__ void __launch_bounds__(256, 2)
k_all(const float4* __restrict__ x4,
      const float* __restrict__ w_pos, const float* __restrict__ w_neg,
      const float* __restrict__ n_param,
      const float* __restrict__ b_pos, const float* __restrict__ b_neg,
      float4* __restrict__ out) {
    __shared__ __align__(16) float phi_s[SRMAX * 4 * BATCH];   // 28 KB
    __shared__ __align__(16) float coef_s[SRMAX * 4 * JT];     // 14 KB
    __shared__ unsigned int s_ticket;

    const int tid = threadIdx.x;
    const int bid = blockIdx.y * NJT + blockIdx.x;
    const int g   = bid * 256 + tid;

    // ================= prologue =================
    const float4* wp4 = reinterpret_cast<const float4*>(w_pos);
    const float4* wn4 = reinterpret_cast<const float4*>(w_neg);
    float m = 0.5f;   // bias value always present
    for (int idx = g; idx < 2 * W_F4; idx += NTHR) {
        float4 a = (idx < W_F4) ? wp4[idx] : wn4[idx - W_F4];
        m = fmaxf(m, fmaxf(fmaxf(fabsf(a.x), fabsf(a.y)),
                           fmaxf(fabsf(a.z), fabsf(a.w))));
    }
    for (int idx = g; idx < X_F4; idx += NTHR) {
        float4 xv = x4[idx];
        int b = idx >> 8;
        int i = (idx & 255) * 4;
        g_lvT[(i + 0) * BATCH + b] = fmaxf(lg2f_(2.0f * fminf(fmaxf(xv.x, 0.0f), 1.0f)), -8.0f);
        g_lvT[(i + 1) * BATCH + b] = fmaxf(lg2f_(2.0f * fminf(fmaxf(xv.y, 0.0f), 1.0f)), -8.0f);
        g_lvT[(i + 2) * BATCH + b] = fmaxf(lg2f_(2.0f * fminf(fmaxf(xv.z, 0.0f), 1.0f)), -8.0f);
        g_lvT[(i + 3) * BATCH + b] = fmaxf(lg2f_(2.0f * fminf(fmaxf(xv.w, 0.0f), 1.0f)), -8.0f);
    }
    #pragma unroll
    for (int o = 16; o; o >>= 1) m = fmaxf(m, __shfl_xor_sync(0xffffffffu, m, o));
    {
        float* sm = coef_s;
        const int lane = tid & 31, w = tid >> 5;
        if (lane == 0) sm[w] = m;
        __syncthreads();
        if (tid == 0) {
            #pragma unroll
            for (int i = 1; i < 8; i++) m = fmaxf(m, sm[i]);
            atomicMax(&g_max_bits, __float_as_int(m));
        }
    }
    global_gate(&g_gate1, tid);
    // ================= main compute =================

    const int jq    = tid & 15;
    const int bbase = (tid >> 4) * 8;
    const int j0    = blockIdx.x * JT;
    const int ch    = blockIdx.y;
    const float cG  = __int_as_float(g_max_bits) * (1.0f / 9.0f);

    float acc[4][8];
    #pragma unroll
    for (int j = 0; j < 4; j++)
        #pragma unroll
        for (int b = 0; b < 8; b++) acc[j][b] = 0.0f;

    if (ch < 36) {
        int i0 = ch * 28;
        stage_rows<14>(w_pos, w_neg, n_param, phi_s, coef_s, i0,      j0, tid, jq, bbase, cG, acc);
        stage_rows<14>(w_pos, w_neg, n_param, phi_s, coef_s, i0 + 14, j0, tid, jq, bbase, cG, acc);
    } else {
        stage_rows<8>(w_pos, w_neg, n_param, phi_s, coef_s, 1008, j0, tid, jq, bbase, cG, acc);
        stage_rows<8>(w_pos, w_neg, n_param, phi_s, coef_s, 1016, j0, tid, jq, bbase, cG, acc);
    }

    float* outp = &g_partial[ch * (BATCH * NOUT)];
    #pragma unroll
    for (int b = 0; b < 8; b++) {
        float4 v = make_float4(acc[0][b], acc[1][b], acc[2][b], acc[3][b]);
        *reinterpret_cast<float4*>(&outp[(bbase + b) * NOUT + j0 + jq * 4]) = v;
    }

    // ============ per-column ticket; last arrival reduces the column ============
    __threadfence();
    __syncthreads();
    if (tid == 0) s_ticket = atomicAdd(&g_colcnt[blockIdx.x], 1u);
    __syncthreads();
    if (s_ticket % NCH != NCH - 1) return;   // not the 37th arrival of this replay
    __threadfence();                          // acquire: all column partials visible

    // This CTA reduces column blockIdx.x: outputs 128b x 64j = 2048 float4.
    const float4* gp = reinterpret_cast<const float4*>(g_partial);
    const int jf0 = j0 >> 2;                  // first f4 of this column in a row
    #pragma unroll
    for (int r = 0; r < 8; r++) {
        int idx = tid * 8 + r;                // 0..2047
        int b   = idx >> 4;
        int q   = idx & 15;
        int o   = b * ROWF4 + jf0 + q;        // output f4 index
        float4 s = make_float4(0.0f, 0.0f, 0.0f, 0.0f);
        #pragma unroll
        for (int c = 0; c < NCH; c++) {       // fixed order -> deterministic
            float4 v = gp[c * (BATCH * ROWF4) + o];
            s.x += v.x; s.y += v.y; s.z += v.z; s.w += v.w;
        }
        // exact bias term: vr = 2 -> vr^(lg2 n + 1) = 2n -> term = (|b|+cG)*n
        const int j = j0 + q * 4;
        float4 bp = *reinterpret_cast<const float4*>(&b_pos[j]);
        float4 bn = *reinterpret_cast<const float4*>(&b_neg[j]);
        const float* nrow = n_param + (size_t)NIN * (2 * NOUT);
        float4 n0 = *reinterpret_cast<const float4*>(&nrow[2 * j]);
        float4 n1 = *reinterpret_cast<const float4*>(&nrow[2 * j + 4]);
        s.x += (fabsf(bp.x) + cG) * n0.x - (fabsf(bn.x) + cG) * n0.y;
        s.y += (fabsf(bp.y) + cG) * n0.z - (fabsf(bn.y) + cG) * n0.w;
        s.z += (fabsf(bp.z) + cG) * n1.x - (fabsf(bn.z) + cG) * n1.y;
        s.w += (fabsf(bp.w) + cG) * n1.z - (fabsf(bn.w) + cG) * n1.w;
        out[o] = s;
    }
}

// ---------------------------------------------------------------------------
extern "C" void kernel_launch(void* const* d_in, const int* in_sizes, int n_in,
                              void* d_out, int out_size) {
    const float* x       = (const float*)d_in[0];
    const float* w_pos   = (const float*)d_in[1];
    const float* w_neg   = (const float*)d_in[2];
    const float* b_pos   = (const float*)d_in[3];
    const float* b_neg   = (const float*)d_in[4];
    const float* n_param = (const float*)d_in[5];

    dim3 grid(NJT, NCH);     // 8 x 37 = 296 = 148*2, all co-resident at occ 2
    k_all<<<grid, 256>>>((const float4*)x, w_pos, w_neg, n_param,
                         b_pos, b_neg, (float4*)d_out);
}

// round 12
// speedup vs baseline: 2.4357x; 2.4357x over previous
#include <cuda_runtime.h>

#define BATCH 128
#define NIN   1024
#define NOUT  512
#define JT    64
#define NJT   (NOUT / JT)    // 8
#define NCH   37             // 36 chunks of 28 + 1 of 16 ; grid 8*37 = 296 = 148*2
#define NBLK  296
#define NTHR  (NBLK * 256)   // 75776
#define SRMAX 14
#define E0    2.1245f
#define LN2   0.69314718f
#define W_F4  131072         // float4 count per w array
#define X_F4  32768          // float4 count of x
#define OUTF4 (BATCH * NOUT / 4)   // 16384

__device__ int          g_max_bits;              // zero-init; monotone -> replay-stable
__device__ unsigned int g_gate1;                 // monotone ticket counter (never reset)
__device__ float        g_lvT[NIN * BATCH];      // transposed clamped lg2 input

__device__ __forceinline__ float ex2f_(float x) {
    float y; asm("ex2.approx.f32 %0, %1;" : "=f"(y) : "f"(x)); return y;
}
__device__ __forceinline__ float lg2f_(float x) {
    float y; asm("lg2.approx.f32 %0, %1;" : "=f"(y) : "f"(x)); return y;
}

// Monotone-ticket global barrier (replay-safe, no reset needed).
__device__ __forceinline__ void global_gate(unsigned int* ctr, int tid) {
    __syncthreads();
    if (tid == 0) {
        __threadfence();
        unsigned int t = atomicAdd(ctr, 1u);
        unsigned int target = (t / NBLK + 1u) * NBLK;
        while (*reinterpret_cast<volatile unsigned int*>(ctr) < target)
            __nanosleep(32);
    }
    __syncthreads();
    __threadfence();
}

// ---------------------------------------------------------------------------
// Staged compute: Taylor K=4, register-blocked 4j x 8b per thread (FFMA-bound)
// ---------------------------------------------------------------------------
template<int SR>
__device__ __forceinline__ void stage_rows(
    const float* __restrict__ w_pos, const float* __restrict__ w_neg,
    const float* __restrict__ n_param,
    float* phi_s, float* coef_s,
    int i0, int j0, int tid, int jq, int bbase, float cG, float (*acc)[8])
{
    __syncthreads();
    // ---- stage phi[ii][k][b]
    constexpr int TOT_LV = SR * BATCH;
    #pragma unroll
    for (int r = 0; r < (TOT_LV + 255) / 256; r++) {
        int idx = r * 256 + tid;
        if ((TOT_LV % 256 == 0) || idx < TOT_LV) {
            int ii = idx >> 7;
            int b  = idx & 127;
            float lv = g_lvT[(i0 + ii) * BATCH + b];
            float p0 = ex2f_(E0 * lv);
            float L  = lv * LN2;
            float p1 = p0 * L;
            float p2 = p1 * (L * 0.5f);
            float p3 = p2 * (L * 0.33333333f);
            float* dst = &phi_s[ii * 512 + b];
            dst[0]   = p0;
            dst[128] = p1;
            dst[256] = p2;
            dst[384] = p3;
        }
    }
    // ---- stage C_k at coef[ii][k][j]
    constexpr int TOT_CF = SR * JT;
    #pragma unroll
    for (int r = 0; r < (TOT_CF + 255) / 256; r++) {
        int idx = r * 256 + tid;
        if ((TOT_CF % 256 == 0) || idx < TOT_CF) {
            int ii = idx >> 6, jj = idx & 63;
            int i = i0 + ii, j = j0 + jj;
            float cp = 0.5f * (fabsf(w_pos[i * NOUT + j]) + cG);
            float cn = 0.5f * (fabsf(w_neg[i * NOUT + j]) + cG);
            float2 np = reinterpret_cast<const float2*>(n_param)[i * NOUT + j];
            float ep = lg2f_(np.x) + 1.0f - E0;
            float en = lg2f_(np.y) + 1.0f - E0;
            float* dst = &coef_s[ii * 256 + jj];
            dst[0]   = cp - cn;
            dst[64]  = cp * ep - cn * en;
            dst[128] = cp * ep * ep - cn * en * en;
            dst[192] = cp * ep * ep * ep - cn * en * en * en;
        }
    }
    __syncthreads();

    // ---- inner loop: 12 LDS.128 / 128 FFMA per thread*ii -> FFMA-bound
    #pragma unroll 2
    for (int ii = 0; ii < SR; ii++) {
        const float* cb = &coef_s[ii * 256 + jq * 4];
        const float* pb = &phi_s[ii * 512 + bbase];
        #pragma unroll
        for (int k = 0; k < 4; k++) {
            float4 c  = *reinterpret_cast<const float4*>(cb + k * 64);
            float4 pa = *reinterpret_cast<const float4*>(pb + k * 128);
            float4 pc = *reinterpret_cast<const float4*>(pb + k * 128 + 4);
            const float cv[4] = {c.x, c.y, c.z, c.w};
            const float pv[8] = {pa.x, pa.y, pa.z, pa.w, pc.x, pc.y, pc.z, pc.w};
            #pragma unroll
            for (int j = 0; j < 4; j++)
                #pragma unroll
                for (int b = 0; b < 8; b++)
                    acc[j][b] = fmaf(cv[j], pv[b], acc[j][b]);
        }
    }
}

// ---------------------------------------------------------------------------
// Single persistent kernel: prologue (max|w| + lvT + zero d_out) -> gate1 ->
// compute -> REDG-accumulate directly into d_out. No partials, no 2nd gate.
// ---------------------------------------------------------------------------
__global__ void __launch_bounds__(256, 2)
k_all(const float4* __restrict__ x4,
      const float* __restrict__ w_pos, const float* __restrict__ w_neg,
      const float* __restrict__ n_param,
      const float* __restrict__ b_pos, const float* __restrict__ b_neg,
      float* __restrict__ out) {
    __shared__ __align__(16) float phi_s[SRMAX * 4 * BATCH];   // 28 KB
    __shared__ __align__(16) float coef_s[SRMAX * 4 * JT];     // 14 KB

    const int tid = threadIdx.x;
    const int bid = blockIdx.y * NJT + blockIdx.x;
    const int g   = bid * 256 + tid;

    // ================= prologue =================
    // zero d_out slice (ordered before all REDG by gate1)
    if (g < OUTF4)
        reinterpret_cast<float4*>(out)[g] = make_float4(0.0f, 0.0f, 0.0f, 0.0f);

    const float4* wp4 = reinterpret_cast<const float4*>(w_pos);
    const float4* wn4 = reinterpret_cast<const float4*>(w_neg);
    float m = 0.5f;   // bias value always present
    for (int idx = g; idx < 2 * W_F4; idx += NTHR) {
        float4 a = (idx < W_F4) ? wp4[idx] : wn4[idx - W_F4];
        m = fmaxf(m, fmaxf(fmaxf(fabsf(a.x), fabsf(a.y)),
                           fmaxf(fabsf(a.z), fabsf(a.w))));
    }
    for (int idx = g; idx < X_F4; idx += NTHR) {
        float4 xv = x4[idx];
        int b = idx >> 8;
        int i = (idx & 255) * 4;
        g_lvT[(i + 0) * BATCH + b] = fmaxf(lg2f_(2.0f * fminf(fmaxf(xv.x, 0.0f), 1.0f)), -8.0f);
        g_lvT[(i + 1) * BATCH + b] = fmaxf(lg2f_(2.0f * fminf(fmaxf(xv.y, 0.0f), 1.0f)), -8.0f);
        g_lvT[(i + 2) * BATCH + b] = fmaxf(lg2f_(2.0f * fminf(fmaxf(xv.z, 0.0f), 1.0f)), -8.0f);
        g_lvT[(i + 3) * BATCH + b] = fmaxf(lg2f_(2.0f * fminf(fmaxf(xv.w, 0.0f), 1.0f)), -8.0f);
    }
    #pragma unroll
    for (int o = 16; o; o >>= 1) m = fmaxf(m, __shfl_xor_sync(0xffffffffu, m, o));
    {
        float* sm = coef_s;
        const int lane = tid & 31, w = tid >> 5;
        if (lane == 0) sm[w] = m;
        __syncthreads();
        if (tid == 0) {
            #pragma unroll
            for (int i = 1; i < 8; i++) m = fmaxf(m, sm[i]);
            atomicMax(&g_max_bits, __float_as_int(m));
        }
    }
    global_gate(&g_gate1, tid);
    // ================= main compute =================

    const int jq    = tid & 15;
    const int bbase = (tid >> 4) * 8;
    const int j0    = blockIdx.x * JT;
    const int ch    = blockIdx.y;
    const float cG  = __int_as_float(g_max_bits) * (1.0f / 9.0f);

    float acc[4][8];
    #pragma unroll
    for (int j = 0; j < 4; j++)
        #pragma unroll
        for (int b = 0; b < 8; b++) acc[j][b] = 0.0f;

    if (ch < 36) {
        int i0 = ch * 28;
        stage_rows<14>(w_pos, w_neg, n_param, phi_s, coef_s, i0,      j0, tid, jq, bbase, cG, acc);
        stage_rows<14>(w_pos, w_neg, n_param, phi_s, coef_s, i0 + 14, j0, tid, jq, bbase, cG, acc);
    } else {
        stage_rows<8>(w_pos, w_neg, n_param, phi_s, coef_s, 1008, j0, tid, jq, bbase, cG, acc);
        stage_rows<8>(w_pos, w_neg, n_param, phi_s, coef_s, 1016, j0, tid, jq, bbase, cG, acc);

        // fold exact bias term (b-independent) into the last chunk's acc:
        // vr = 2 exactly -> vr^(lg2 n + 1) = 2n -> term = (|b|+cG)*n
        const float* nrow = n_param + (size_t)NIN * (2 * NOUT);
        #pragma unroll
        for (int q = 0; q < 4; q++) {
            int j = j0 + jq * 4 + q;
            float t = (fabsf(b_pos[j]) + cG) * nrow[2 * j]
                    - (fabsf(b_neg[j]) + cG) * nrow[2 * j + 1];
            #pragma unroll
            for (int b = 0; b < 8; b++) acc[q][b] += t;
        }
    }

    // ================= REDG accumulate into d_out =================
    #pragma unroll
    for (int b = 0; b < 8; b++) {
        float* o = &out[(bbase + b) * NOUT + j0 + jq * 4];
        atomicAdd(o + 0, acc[0][b]);
        atomicAdd(o + 1, acc[1][b]);
        atomicAdd(o + 2, acc[2][b]);
        atomicAdd(o + 3, acc[3][b]);
    }
}

// ---------------------------------------------------------------------------
extern "C" void kernel_launch(void* const* d_in, const int* in_sizes, int n_in,
                              void* d_out, int out_size) {
    const float* x       = (const float*)d_in[0];
    const float* w_pos   = (const float*)d_in[1];
    const float* w_neg   = (const float*)d_in[2];
    const float* b_pos   = (const float*)d_in[3];
    const float* b_neg   = (const float*)d_in[4];
    const float* n_param = (const float*)d_in[5];

    dim3 grid(NJT, NCH);     // 8 x 37 = 296 = 148*2, all co-resident at occ 2
    k_all<<<grid, 256>>>((const float4*)x, w_pos, w_neg, n_param,
                         b_pos, b_neg, (float*)d_out);
}

// round 13
// speedup vs baseline: 2.6015x; 1.0681x over previous
#include <cuda_runtime.h>

#define BATCH 128
#define NIN   1024
#define NOUT  512
#define JT    64
#define NJT   (NOUT / JT)    // 8
#define NCH   37             // 36 chunks of 28 rows + 1 of 16 ; grid 8*37 = 296 = 148*2
#define NBLK  296
#define NTHR  (NBLK * 256)
#define E0    2.1245f
#define LN2   0.69314718f
#define X_F4  32768
#define OUTF4 (BATCH * NOUT / 4)   // 16384
#define ROWF4 (NOUT / 4)           // 128

__device__ int          g_max_bits;              // zero-init; monotone -> replay-stable
__device__ unsigned int g_gate1, g_gate2;        // monotone ticket counters (never reset)
__device__ float        g_lvT[NIN * BATCH];
__device__ float        g_partial[NCH * BATCH * NOUT];

__device__ __forceinline__ float ex2f_(float x) {
    float y; asm("ex2.approx.f32 %0, %1;" : "=f"(y) : "f"(x)); return y;
}
__device__ __forceinline__ float lg2f_(float x) {
    float y; asm("lg2.approx.f32 %0, %1;" : "=f"(y) : "f"(x)); return y;
}

// Monotone-ticket global barrier (replay-safe, no reset needed).
__device__ __forceinline__ void global_gate(unsigned int* ctr, int tid) {
    __syncthreads();
    if (tid == 0) {
        __threadfence();
        unsigned int t = atomicAdd(ctr, 1u);
        unsigned int target = (t / NBLK + 1u) * NBLK;
        while (*reinterpret_cast<volatile unsigned int*>(ctr) < target)
            __nanosleep(32);
    }
    __syncthreads();
    __threadfence();
}

// ---- prefetch loads (registers), SR in {7, 8} ----
template<int SR>
__device__ __forceinline__ void load_lv(int i0, int tid, float* lv) {
    #pragma unroll
    for (int r = 0; r < (SR * 128 + 255) / 256; r++) {
        int idx = r * 256 + tid;
        if ((SR * 128) % 256 == 0 || idx < SR * 128)
            lv[r] = g_lvT[(i0 + (idx >> 7)) * BATCH + (idx & 127)];
    }
}
template<int SR>
__device__ __forceinline__ void load_cf(const float* __restrict__ w_pos,
                                        const float* __restrict__ w_neg,
                                        const float* __restrict__ n_param,
                                        int i0, int j0, int tid,
                                        float* wp, float* wn, float2* np) {
    #pragma unroll
    for (int r = 0; r < (SR * 64 + 255) / 256; r++) {
        int idx = r * 256 + tid;
        if ((SR * 64) % 256 == 0 || idx < SR * 64) {
            int i = i0 + (idx >> 6), j = j0 + (idx & 63);
            wp[r] = w_pos[i * NOUT + j];
            wn[r] = w_neg[i * NOUT + j];
            np[r] = reinterpret_cast<const float2*>(n_param)[i * NOUT + j];
        }
    }
}

// ---- convert + STS for one stage ----
template<int SR>
__device__ __forceinline__ void store_stage(float* phi_s, float* coef_s,
                                            int tid, float cG,
                                            const float* lv, const float* wp,
                                            const float* wn, const float2* np) {
    #pragma unroll
    for (int r = 0; r < (SR * 128 + 255) / 256; r++) {
        int idx = r * 256 + tid;
        if ((SR * 128) % 256 == 0 || idx < SR * 128) {
            int ii = idx >> 7, b = idx & 127;
            float l  = lv[r];
            float p0 = ex2f_(E0 * l);
            float L  = l * LN2;
            float p1 = p0 * L;
            float p2 = p1 * (L * 0.5f);
            float p3 = p2 * (L * 0.33333333f);
            float* dst = &phi_s[ii * 512 + b];
            dst[0] = p0; dst[128] = p1; dst[256] = p2; dst[384] = p3;
        }
    }
    #pragma unroll
    for (int r = 0; r < (SR * 64 + 255) / 256; r++) {
        int idx = r * 256 + tid;
        if ((SR * 64) % 256 == 0 || idx < SR * 64) {
            float cp = 0.5f * (fabsf(wp[r]) + cG);
            float cn = 0.5f * (fabsf(wn[r]) + cG);
            float ep = lg2f_(np[r].x) + 1.0f - E0;
            float en = lg2f_(np[r].y) + 1.0f - E0;
            float* dst = &coef_s[(idx >> 6) * 256 + (idx & 63)];
            dst[0]   = cp - cn;
            dst[64]  = cp * ep - cn * en;
            dst[128] = cp * ep * ep - cn * en * en;
            dst[192] = cp * ep * ep * ep - cn * en * en * en;
        }
    }
}

// ---- inner loop: 12 LDS.128 / 128 FFMA per thread*ii -> FFMA-bound ----
template<int SR>
__device__ __forceinline__ void inner(const float* phi_s, const float* coef_s,
                                      int jq, int bbase, float (*acc)[8]) {
    #pragma unroll
    for (int ii = 0; ii < SR; ii++) {
        const float* cb = &coef_s[ii * 256 + jq * 4];
        const float* pb = &phi_s[ii * 512 + bbase];
        #pragma unroll
        for (int k = 0; k < 4; k++) {
            float4 c  = *reinterpret_cast<const float4*>(cb + k * 64);
            float4 pa = *reinterpret_cast<const float4*>(pb + k * 128);
            float4 pc = *reinterpret_cast<const float4*>(pb + k * 128 + 4);
            const float cv[4] = {c.x, c.y, c.z, c.w};
            const float pv[8] = {pa.x, pa.y, pa.z, pa.w, pc.x, pc.y, pc.z, pc.w};
            #pragma unroll
            for (int j = 0; j < 4; j++)
                #pragma unroll
                for (int b = 0; b < 8; b++)
                    acc[j][b] = fmaf(cv[j], pv[b], acc[j][b]);
        }
    }
}

// ---------------------------------------------------------------------------
// Single persistent kernel:
//  prologue: lvT slice + per-tile max|w| (prewarms this CTA's w tile) ->
//  gate1 -> software-pipelined staged compute -> partials -> gate2 -> reduce.
// ---------------------------------------------------------------------------
__global__ void __launch_bounds__(256, 2)
k_all(const float4* __restrict__ x4,
      const float* __restrict__ w_pos, const float* __restrict__ w_neg,
      const float* __restrict__ n_param,
      const float* __restrict__ b_pos, const float* __restrict__ b_neg,
      float4* __restrict__ out) {
    __shared__ __align__(16) float phi_s[8 * 512];    // 16 KB
    __shared__ __align__(16) float coef_s[8 * 256];   //  8 KB

    const int tid  = threadIdx.x;
    const int col  = blockIdx.x;
    const int ch   = blockIdx.y;
    const int bid  = ch * NJT + col;
    const int g    = bid * 256 + tid;
    const int j0   = col * JT;
    const int i0   = ch * 28;                 // ch==36 -> 1008
    const int rows = (ch < 36) ? 28 : 16;

    // ---- prologue: lvT slice (global strided) ----
    for (int idx = g; idx < X_F4; idx += NTHR) {
        float4 xv = x4[idx];
        int b = idx >> 8;
        int i = (idx & 255) * 4;
        g_lvT[(i + 0) * BATCH + b] = fmaxf(lg2f_(2.0f * fminf(fmaxf(xv.x, 0.0f), 1.0f)), -8.0f);
        g_lvT[(i + 1) * BATCH + b] = fmaxf(lg2f_(2.0f * fminf(fmaxf(xv.y, 0.0f), 1.0f)), -8.0f);
        g_lvT[(i + 2) * BATCH + b] = fmaxf(lg2f_(2.0f * fminf(fmaxf(xv.z, 0.0f), 1.0f)), -8.0f);
        g_lvT[(i + 3) * BATCH + b] = fmaxf(lg2f_(2.0f * fminf(fmaxf(xv.w, 0.0f), 1.0f)), -8.0f);
    }
    // ---- prologue: per-tile max|w| (covers grid exactly once; warms L1/L2) ----
    {
        const float4* wp4 = reinterpret_cast<const float4*>(w_pos);
        const float4* wn4 = reinterpret_cast<const float4*>(w_neg);
        float m = 0.5f;   // bias value always present
        for (int idx = tid; idx < rows * 16; idx += 256) {
            int a = (i0 + (idx >> 4)) * ROWF4 + (j0 >> 2) + (idx & 15);
            float4 A = wp4[a], B = wn4[a];
            m = fmaxf(m, fmaxf(fmaxf(fabsf(A.x), fabsf(A.y)), fmaxf(fabsf(A.z), fabsf(A.w))));
            m = fmaxf(m, fmaxf(fmaxf(fabsf(B.x), fabsf(B.y)), fmaxf(fabsf(B.z), fabsf(B.w))));
        }
        #pragma unroll
        for (int o = 16; o; o >>= 1) m = fmaxf(m, __shfl_xor_sync(0xffffffffu, m, o));
        const int lane = tid & 31, w = tid >> 5;
        if (lane == 0) coef_s[w] = m;
        __syncthreads();
        if (tid == 0) {
            #pragma unroll
            for (int i = 1; i < 8; i++) m = fmaxf(m, coef_s[i]);
            atomicMax(&g_max_bits, __float_as_int(m));
        }
    }

    // ---- prefetch coef stage 0 (independent of gate) ----
    float lvp[4], wpp[2], wnp[2]; float2 npp[2];
    if (ch < 36) load_cf<7>(w_pos, w_neg, n_param, i0, j0, tid, wpp, wnp, npp);
    else         load_cf<8>(w_pos, w_neg, n_param, i0, j0, tid, wpp, wnp, npp);

    __threadfence();
    global_gate(&g_gate1, tid);
    const float cG = __int_as_float(g_max_bits) * (1.0f / 9.0f);

    const int jq    = tid & 15;
    const int bbase = (tid >> 4) * 8;
    float acc[4][8];
    #pragma unroll
    for (int j = 0; j < 4; j++)
        #pragma unroll
        for (int b = 0; b < 8; b++) acc[j][b] = 0.0f;

    // ---- software-pipelined staged compute ----
    if (ch < 36) {
        load_lv<7>(i0, tid, lvp);
        #pragma unroll 1
        for (int s = 0; s < 4; s++) {
            __syncthreads();
            store_stage<7>(phi_s, coef_s, tid, cG, lvp, wpp, wnp, npp);
            __syncthreads();
            if (s < 3) {
                load_lv<7>(i0 + (s + 1) * 7, tid, lvp);
                load_cf<7>(w_pos, w_neg, n_param, i0 + (s + 1) * 7, j0, tid, wpp, wnp, npp);
            }
            inner<7>(phi_s, coef_s, jq, bbase, acc);
        }
    } else {
        load_lv<8>(i0, tid, lvp);
        #pragma unroll 1
        for (int s = 0; s < 2; s++) {
            __syncthreads();
            store_stage<8>(phi_s, coef_s, tid, cG, lvp, wpp, wnp, npp);
            __syncthreads();
            if (s < 1) {
                load_lv<8>(i0 + 8, tid, lvp);
                load_cf<8>(w_pos, w_neg, n_param, i0 + 8, j0, tid, wpp, wnp, npp);
            }
            inner<8>(phi_s, coef_s, jq, bbase, acc);
        }
    }

    // ---- store partials ----
    float* outp = &g_partial[ch * (BATCH * NOUT)];
    #pragma unroll
    for (int b = 0; b < 8; b++) {
        float4 v = make_float4(acc[0][b], acc[1][b], acc[2][b], acc[3][b]);
        *reinterpret_cast<float4*>(&outp[(bbase + b) * NOUT + j0 + jq * 4]) = v;
    }

    __threadfence();
    global_gate(&g_gate2, tid);

    // ---- final reduction (L2-hot partials) + exact bias term ----
    if (g < OUTF4) {
        const float4* gp = reinterpret_cast<const float4*>(g_partial);
        float4 s = make_float4(0.0f, 0.0f, 0.0f, 0.0f);
        #pragma unroll
        for (int c = 0; c < NCH; c++) {
            float4 v = gp[c * OUTF4 + g];
            s.x += v.x; s.y += v.y; s.z += v.z; s.w += v.w;
        }
        // bias row: vr = 2 exactly -> vr^(lg2 n + 1) = 2n -> term = (|b|+cG)*n
        const int j = (g * 4) & (NOUT - 1);
        float4 bp = *reinterpret_cast<const float4*>(&b_pos[j]);
        float4 bn = *reinterpret_cast<const float4*>(&b_neg[j]);
        const float* nrow = n_param + (size_t)NIN * (2 * NOUT);
        float4 n0 = *reinterpret_cast<const float4*>(&nrow[2 * j]);
        float4 n1 = *reinterpret_cast<const float4*>(&nrow[2 * j + 4]);
        s.x += (fabsf(bp.x) + cG) * n0.x - (fabsf(bn.x) + cG) * n0.y;
        s.y += (fabsf(bp.y) + cG) * n0.z - (fabsf(bn.y) + cG) * n0.w;
        s.z += (fabsf(bp.z) + cG) * n1.x - (fabsf(bn.z) + cG) * n1.y;
        s.w += (fabsf(bp.w) + cG) * n1.z - (fabsf(bn.w) + cG) * n1.w;
        out[g] = s;
    }
}

// ---------------------------------------------------------------------------
extern "C" void kernel_launch(void* const* d_in, const int* in_sizes, int n_in,
                              void* d_out, int out_size) {
    const float* x       = (const float*)d_in[0];
    const float* w_pos   = (const float*)d_in[1];
    const float* w_neg   = (const float*)d_in[2];
    const float* b_pos   = (const float*)d_in[3];
    const float* b_neg   = (const float*)d_in[4];
    const float* n_param = (const float*)d_in[5];

    dim3 grid(NJT, NCH);     // 8 x 37 = 296 = 148*2, all co-resident at occ 2
    k_all<<<grid, 256>>>((const float4*)x, w_pos, w_neg, n_param,
                         b_pos, b_neg, (float4*)d_out);
}

// round 14
// speedup vs baseline: 3.2335x; 1.2429x over previous
#include <cuda_runtime.h>
#include <cuda_bf16.h>
#include <cstdint>

#define BATCH 128
#define NIN   1024
#define NOUT  512
#define JT    64
#define NJT   8
#define NCH   37             // 36 chunks of 28 i-rows + 1 of 16 ; grid 8*37 = 296 = 148*2
#define NBLK  296
#define NTHR  (NBLK * 256)
#define E0    2.1245f
#define LN2   0.69314718f
#define X_F4  32768
#define OUTF4 16384
#define ROWF4 128
#define KP    28             // smem K-pitch in u32 (56 bf16) per slab

__device__ int          g_max_bits;              // zero-init; monotone -> replay-stable
__device__ unsigned int g_gate1, g_gate2;        // monotone ticket counters (never reset)
__device__ float        g_lvT[NIN * BATCH];
__device__ float        g_partial[NCH * BATCH * NOUT];

__device__ __forceinline__ float ex2f_(float x) {
    float y; asm("ex2.approx.f32 %0, %1;" : "=f"(y) : "f"(x)); return y;
}
__device__ __forceinline__ float lg2f_(float x) {
    float y; asm("lg2.approx.f32 %0, %1;" : "=f"(y) : "f"(x)); return y;
}
// pack two f32 -> bf16x2 (lo -> low half)
__device__ __forceinline__ uint32_t pkbf2(float lo, float hi) {
    uint32_t r; asm("cvt.rn.bf16x2.f32 %0, %1, %2;" : "=r"(r) : "f"(hi), "f"(lo)); return r;
}
// D += A(16x16 bf16, row) * B(16x8 bf16, col), f32 accumulate
__device__ __forceinline__ void mma16816(float* d, const uint32_t* a, const uint32_t* b) {
    asm volatile(
        "mma.sync.aligned.m16n8k16.row.col.f32.bf16.bf16.f32 "
        "{%0,%1,%2,%3}, {%4,%5,%6,%7}, {%8,%9}, {%0,%1,%2,%3};"
        : "+f"(d[0]), "+f"(d[1]), "+f"(d[2]), "+f"(d[3])
        : "r"(a[0]), "r"(a[1]), "r"(a[2]), "r"(a[3]), "r"(b[0]), "r"(b[1]));
}

// Monotone-ticket global barrier (replay-safe, no reset needed).
__device__ __forceinline__ void global_gate(unsigned int* ctr, int tid) {
    __syncthreads();
    if (tid == 0) {
        __threadfence();
        unsigned int t = atomicAdd(ctr, 1u);
        unsigned int target = (t / NBLK + 1u) * NBLK;
        while (*reinterpret_cast<volatile unsigned int*>(ctr) < target)
            __nanosleep(32);
    }
    __syncthreads();
    __threadfence();
}

// ---------------------------------------------------------------------------
// One K-slab (ROWS i-rows, K = 4*ROWS <= 56): stage A(phi) + B(C) hi/lo in
// fragment-native smem layouts, then HMMA over ROWS/4 k16 steps.
// ---------------------------------------------------------------------------
template<int ROWS>
__device__ __forceinline__ void slab(
    uint32_t* Ah, uint32_t* Al, uint32_t* Bh, uint32_t* Bl,
    const float* __restrict__ w_pos, const float* __restrict__ w_neg,
    const float* __restrict__ n_param,
    int iG0, int j0, int tid, int wid, int g, int q, float cG,
    float (*acc)[4])
{
    __syncthreads();   // previous slab's mma reads done before overwrite
    // ---- stage A: phi_k[b, i] hi/lo bf16, row-major [b][k=4i+kk], pitch 56
    #pragma unroll
    for (int r = 0; r < (ROWS * 128) / 256; r++) {
        int idx = r * 256 + tid;
        int b = idx & 127, i = idx >> 7;
        float lv = g_lvT[(iG0 + i) * BATCH + b];
        float p0 = ex2f_(E0 * lv);
        float L  = lv * LN2;
        float p1 = p0 * L;
        float p2 = p1 * (0.5f * L);
        float p3 = p2 * (0.33333333f * L);
        uint32_t h01 = pkbf2(p0, p1), h23 = pkbf2(p2, p3);
        float f0 = __uint_as_float(h01 << 16);
        float f1 = __uint_as_float(h01 & 0xFFFF0000u);
        float f2 = __uint_as_float(h23 << 16);
        float f3 = __uint_as_float(h23 & 0xFFFF0000u);
        uint32_t l01 = pkbf2(p0 - f0, p1 - f1), l23 = pkbf2(p2 - f2, p3 - f3);
        int widx = b * KP + 2 * i;
        *reinterpret_cast<uint2*>(Ah + widx) = make_uint2(h01, h23);
        *reinterpret_cast<uint2*>(Al + widx) = make_uint2(l01, l23);
    }
    // ---- stage B: C_k[i, j] hi/lo bf16, [n=j][k=4i+kk], pitch 56
    #pragma unroll
    for (int r = 0; r < (ROWS * 64) / 256; r++) {
        int idx = r * 256 + tid;
        int j = idx & 63, i = idx >> 6;
        int ig = iG0 + i, jg = j0 + j;
        float cp = 0.5f * (fabsf(w_pos[ig * NOUT + jg]) + cG);
        float cn = 0.5f * (fabsf(w_neg[ig * NOUT + jg]) + cG);
        float2 np = reinterpret_cast<const float2*>(n_param)[ig * NOUT + jg];
        float ep = lg2f_(np.x) + 1.0f - E0;
        float en = lg2f_(np.y) + 1.0f - E0;
        float ep2 = ep * ep, en2 = en * en;
        float C0 = cp - cn;
        float C1 = cp * ep - cn * en;
        float C2 = cp * ep2 - cn * en2;
        float C3 = cp * ep2 * ep - cn * en2 * en;
        uint32_t h01 = pkbf2(C0, C1), h23 = pkbf2(C2, C3);
        float f0 = __uint_as_float(h01 << 16);
        float f1 = __uint_as_float(h01 & 0xFFFF0000u);
        float f2 = __uint_as_float(h23 << 16);
        float f3 = __uint_as_float(h23 & 0xFFFF0000u);
        uint32_t l01 = pkbf2(C0 - f0, C1 - f1), l23 = pkbf2(C2 - f2, C3 - f3);
        int widx = j * KP + 2 * i;
        *reinterpret_cast<uint2*>(Bh + widx) = make_uint2(h01, h23);
        *reinterpret_cast<uint2*>(Bl + widx) = make_uint2(l01, l23);
    }
    __syncthreads();

    // ---- HMMA: warp wid = M-strip rows 16w..16w+15; 8 n8-tiles; NK k16 steps
    constexpr int NK = ROWS / 4;
    const int arow = 16 * wid + g;
    #pragma unroll
    for (int s = 0; s < NK; s++) {
        int ai = arow * KP + 8 * s + q;
        uint32_t ah[4] = {Ah[ai], Ah[ai + 8 * KP], Ah[ai + 4], Ah[ai + 8 * KP + 4]};
        uint32_t al[4] = {Al[ai], Al[ai + 8 * KP], Al[ai + 4], Al[ai + 8 * KP + 4]};
        #pragma unroll
        for (int nt = 0; nt < 8; nt++) {
            int bi = (8 * nt + g) * KP + 8 * s + q;
            uint32_t bh[2] = {Bh[bi], Bh[bi + 4]};
            uint32_t bl[2] = {Bl[bi], Bl[bi + 4]};
            mma16816(acc[nt], ah, bh);
            mma16816(acc[nt], ah, bl);
            mma16816(acc[nt], al, bh);
        }
    }
}

// ---------------------------------------------------------------------------
// Single persistent kernel: prologue (lvT + per-tile max|w|) -> gate1 ->
// tensor-core GEMM on Taylor basis -> partials -> gate2 -> L2-hot reduce.
// ---------------------------------------------------------------------------
__global__ void __launch_bounds__(256, 2)
k_all(const float4* __restrict__ x4,
      const float* __restrict__ w_pos, const float* __restrict__ w_neg,
      const float* __restrict__ n_param,
      const float* __restrict__ b_pos, const float* __restrict__ b_neg,
      float4* __restrict__ out) {
    __shared__ __align__(16) uint32_t Ah[128 * KP], Al[128 * KP];  // 28.7 KB
    __shared__ __align__(16) uint32_t Bh[64 * KP],  Bl[64 * KP];   // 14.3 KB
    __shared__ float sred[8];

    const int tid = threadIdx.x;
    const int col = blockIdx.x;
    const int ch  = blockIdx.y;
    const int bid = ch * NJT + col;
    const int gg  = bid * 256 + tid;
    const int j0  = col * JT;
    const int i0  = ch * 28;
    const int rows = (ch < 36) ? 28 : 16;

    // ---- prologue: lvT slice (global strided) ----
    for (int idx = gg; idx < X_F4; idx += NTHR) {
        float4 xv = x4[idx];
        int b = idx >> 8;
        int i = (idx & 255) * 4;
        g_lvT[(i + 0) * BATCH + b] = fmaxf(lg2f_(2.0f * fminf(fmaxf(xv.x, 0.0f), 1.0f)), -8.0f);
        g_lvT[(i + 1) * BATCH + b] = fmaxf(lg2f_(2.0f * fminf(fmaxf(xv.y, 0.0f), 1.0f)), -8.0f);
        g_lvT[(i + 2) * BATCH + b] = fmaxf(lg2f_(2.0f * fminf(fmaxf(xv.z, 0.0f), 1.0f)), -8.0f);
        g_lvT[(i + 3) * BATCH + b] = fmaxf(lg2f_(2.0f * fminf(fmaxf(xv.w, 0.0f), 1.0f)), -8.0f);
    }
    // ---- prologue: per-tile max|w| (covers grid exactly once; warms L2) ----
    {
        const float4* wp4 = reinterpret_cast<const float4*>(w_pos);
        const float4* wn4 = reinterpret_cast<const float4*>(w_neg);
        float m = 0.5f;   // bias value always present
        for (int idx = tid; idx < rows * 16; idx += 256) {
            int a = (i0 + (idx >> 4)) * ROWF4 + (j0 >> 2) + (idx & 15);
            float4 A = wp4[a], B = wn4[a];
            m = fmaxf(m, fmaxf(fmaxf(fabsf(A.x), fabsf(A.y)), fmaxf(fabsf(A.z), fabsf(A.w))));
            m = fmaxf(m, fmaxf(fmaxf(fabsf(B.x), fabsf(B.y)), fmaxf(fabsf(B.z), fabsf(B.w))));
        }
        #pragma unroll
        for (int o = 16; o; o >>= 1) m = fmaxf(m, __shfl_xor_sync(0xffffffffu, m, o));
        const int lane = tid & 31, w = tid >> 5;
        if (lane == 0) sred[w] = m;
        __syncthreads();
        if (tid == 0) {
            #pragma unroll
            for (int i = 1; i < 8; i++) m = fmaxf(m, sred[i]);
            atomicMax(&g_max_bits, __float_as_int(m));
        }
    }
    global_gate(&g_gate1, tid);
    const float cG = __int_as_float(g_max_bits) * (1.0f / 9.0f);

    // ---- tensor-core GEMM over this CTA's (chunk, column) tile ----
    const int wid = tid >> 5;
    const int g   = (tid & 31) >> 2;   // lane/4
    const int q   = tid & 3;           // lane%4
    float acc[8][4];
    #pragma unroll
    for (int nt = 0; nt < 8; nt++)
        #pragma unroll
        for (int c = 0; c < 4; c++) acc[nt][c] = 0.0f;

    if (ch < 36) {
        slab<12>(Ah, Al, Bh, Bl, w_pos, w_neg, n_param, i0,      j0, tid, wid, g, q, cG, acc);
        slab<12>(Ah, Al, Bh, Bl, w_pos, w_neg, n_param, i0 + 12, j0, tid, wid, g, q, cG, acc);
        slab<4> (Ah, Al, Bh, Bl, w_pos, w_neg, n_param, i0 + 24, j0, tid, wid, g, q, cG, acc);
    } else {
        slab<12>(Ah, Al, Bh, Bl, w_pos, w_neg, n_param, 1008, j0, tid, wid, g, q, cG, acc);
        slab<4> (Ah, Al, Bh, Bl, w_pos, w_neg, n_param, 1020, j0, tid, wid, g, q, cG, acc);
    }

    // ---- store partials from fragments ----
    {
        float* outp = &g_partial[ch * (BATCH * NOUT)];
        const int b0 = 16 * wid + g;
        #pragma unroll
        for (int nt = 0; nt < 8; nt++) {
            int j = j0 + 8 * nt + 2 * q;
            *reinterpret_cast<float2*>(&outp[b0 * NOUT + j])       = make_float2(acc[nt][0], acc[nt][1]);
            *reinterpret_cast<float2*>(&outp[(b0 + 8) * NOUT + j]) = make_float2(acc[nt][2], acc[nt][3]);
        }
    }

    __threadfence();
    global_gate(&g_gate2, tid);

    // ---- final reduction (L2-hot partials) + exact bias term ----
    if (gg < OUTF4) {
        const float4* gp = reinterpret_cast<const float4*>(g_partial);
        float4 s = make_float4(0.0f, 0.0f, 0.0f, 0.0f);
        #pragma unroll
        for (int c = 0; c < NCH; c++) {
            float4 v = gp[c * OUTF4 + gg];
            s.x += v.x; s.y += v.y; s.z += v.z; s.w += v.w;
        }
        // bias row: vr = 2 exactly -> vr^(lg2 n + 1) = 2n -> term = (|b|+cG)*n
        const int j = (gg * 4) & (NOUT - 1);
        float4 bp = *reinterpret_cast<const float4*>(&b_pos[j]);
        float4 bn = *reinterpret_cast<const float4*>(&b_neg[j]);
        const float* nrow = n_param + (size_t)NIN * (2 * NOUT);
        float4 n0 = *reinterpret_cast<const float4*>(&nrow[2 * j]);
        float4 n1 = *reinterpret_cast<const float4*>(&nrow[2 * j + 4]);
        s.x += (fabsf(bp.x) + cG) * n0.x - (fabsf(bn.x) + cG) * n0.y;
        s.y += (fabsf(bp.y) + cG) * n0.z - (fabsf(bn.y) + cG) * n0.w;
        s.z += (fabsf(bp.z) + cG) * n1.x - (fabsf(bn.z) + cG) * n1.y;
        s.w += (fabsf(bp.w) + cG) * n1.z - (fabsf(bn.w) + cG) * n1.w;
        out[gg] = s;
    }
}

// ---------------------------------------------------------------------------
extern "C" void kernel_launch(void* const* d_in, const int* in_sizes, int n_in,
                              void* d_out, int out_size) {
    const float* x       = (const float*)d_in[0];
    const float* w_pos   = (const float*)d_in[1];
    const float* w_neg   = (const float*)d_in[2];
    const float* b_pos   = (const float*)d_in[3];
    const float* b_neg   = (const float*)d_in[4];
    const float* n_param = (const float*)d_in[5];

    dim3 grid(NJT, NCH);     // 8 x 37 = 296 = 148*2, all co-resident at occ 2
    k_all<<<grid, 256>>>((const float4*)x, w_pos, w_neg, n_param,
                         b_pos, b_neg, (float4*)d_out);
}